// round 15
// baseline (speedup 1.0000x reference)
#include <cuda_runtime.h>

// ---------------------------------------------------------------------------
// LBP histogram kernel, GB300 sm_103a — round 14
// img: [16,3,1024,1024] fp32 -> out: [1,256] fp32 standardized histogram
// 128-thread blocks x 7/SM (28 warps), hot-code (0/255) register counters,
// prmt+dp4a code builder, XOR-swizzled per-thread byte histograms
// (128 B/code block -> code<<7, R13's <<8 was the OOB bug), one row-segment
// per warp, fused finalize.
// ---------------------------------------------------------------------------

#define IMG_H 1024
#define IMG_W 1024
#define HW (IMG_H * IMG_W)
#define W4 (IMG_W >> 2)

#define THREADS 128
#define BLOCKS 1036                 // 148 SMs * 7 blocks = one full wave
#define WARPS_TOTAL (BLOCKS * 4)    // 4144
// 128 (image,strip) columns; 48 cols -> 33 row-segments, 80 cols -> 32:
// 48*33 + 80*32 = 4144 segments == total warps. One segment per warp.
#define COLS_33 48
#define HIST_BYTES (256 * THREADS)  // 32 KB

__device__ unsigned int g_count[256];
__device__ unsigned int g_done;

struct Row { float4 g; float l, r; };
struct Raw { float4 r, g, b; float hr, hg, hb; };

__device__ __forceinline__ float gray1(float r, float g, float b) {
    return fmaf(0.114f, b, fmaf(0.587f, g, 0.299f * r));
}

// PTX prmt.b32 default mode: selector nibble 0x8|i replicates the sign (msb)
// of source byte i across the destination byte (PTX ISA guaranteed).
template <unsigned SEL>
__device__ __forceinline__ unsigned prmt(unsigned a, unsigned b) {
    unsigned d;
    asm("prmt.b32 %0, %1, %2, %3;" : "=r"(d) : "r"(a), "r"(b), "n"(SEL));
    return d;
}

// Steady-state row load: unconditional bulk, predicated halo (warp-constant).
__device__ __forceinline__ Raw load_fast(const float4* __restrict__ p,
                                         const float* __restrict__ qh,
                                         bool ph) {
    Raw o;
    o.r = p[0];
    o.g = p[HW >> 2];
    o.b = p[HW >> 1];
    o.hr = o.hg = o.hb = 0.f;
    if (ph) { o.hr = qh[0]; o.hg = qh[HW]; o.hb = qh[2 * HW]; }
    return o;
}

// Edge row load: zero-fills out-of-range / out-of-segment rows.
__device__ __forceinline__ Raw load_guard(const float4* __restrict__ p,
                                          const float* __restrict__ qh,
                                          bool ph, int x, int rb) {
    Raw o;
    o.r = o.g = o.b = make_float4(0.f, 0.f, 0.f, 0.f);
    o.hr = o.hg = o.hb = 0.f;
    if ((unsigned)x < (unsigned)IMG_H && x <= rb) {
        o.r = p[0];
        o.g = p[HW >> 2];
        o.b = p[HW >> 1];
        if (ph) { o.hr = qh[0]; o.hg = qh[HW]; o.hb = qh[2 * HW]; }
    }
    return o;
}

// Convert a raw row (loaded ~2 iterations ago) to gray + neighbor shuffles.
__device__ __forceinline__ Row conv(const Raw& a, int lane) {
    Row o;
    o.g.x = gray1(a.r.x, a.g.x, a.b.x);
    o.g.y = gray1(a.r.y, a.g.y, a.b.y);
    o.g.z = gray1(a.r.z, a.g.z, a.b.z);
    o.g.w = gray1(a.r.w, a.g.w, a.b.w);
    float h = gray1(a.hr, a.hg, a.hb);      // 0 when no halo
    float sl = __shfl_up_sync(0xffffffffu, o.g.w, 1);
    float sr = __shfl_down_sync(0xffffffffu, o.g.x, 1);
    o.l = (lane == 0) ? h : sl;
    o.r = (lane == 31) ? h : sr;
    return o;
}

// LBP code via prmt sign-replication + DP4A byte-sum.
// bit_i = (n_i >= c) = NOT sign(n_i - c); grays >= 0, x-x = +0, so exact.
// Codes 0 and 255 (~11% each on this input) are counted in registers; only
// the remaining ~78% touch the smem histogram.
__device__ __forceinline__ void upd(unsigned char* __restrict__ hist, int tid,
                                    unsigned& hot0, unsigned& hot255,
                                    float c, float tl, float t, float tr,
                                    float l, float rr, float bl, float b,
                                    float br) {
    unsigned d0 = __float_as_uint(tr - c);   // bit 0
    unsigned d1 = __float_as_uint(rr - c);   // bit 1
    unsigned d2 = __float_as_uint(br - c);   // bit 2
    unsigned d3 = __float_as_uint(b  - c);   // bit 3
    unsigned d4 = __float_as_uint(bl - c);   // bit 4
    unsigned d5 = __float_as_uint(l  - c);   // bit 5
    unsigned d6 = __float_as_uint(tl - c);   // bit 6
    unsigned d7 = __float_as_uint(t  - c);   // bit 7
    unsigned p01 = prmt<0x00FBu>(d0, d1);
    unsigned p23 = prmt<0xFB00u>(d2, d3);
    unsigned mlo = prmt<0x7610u>(p01, p23);  // [s0,s1,s2,s3]
    unsigned p45 = prmt<0x00FBu>(d4, d5);
    unsigned p67 = prmt<0xFB00u>(d6, d7);
    unsigned mhi = prmt<0x7610u>(p45, p67);  // [s4,s5,s6,s7]
    unsigned lo = ~mlo & 0x08040201u;
    unsigned hi = ~mhi & 0x80402010u;
    unsigned code = __dp4a(lo, 0x01010101u, __dp4a(hi, 0x01010101u, 0u));
    hot0   += (code == 0u);
    hot255 += (code == 255u);
    if (code - 1u < 254u)   // predicated RMW, no branch
        hist[(code << 7) + (tid ^ ((code << 2) & 127u))]++;  // 128 B/code
}

#define DO4UPDS()                                                        \
    do {                                                                 \
        upd(hist, tid, hot0, hot255, mid.g.x, top.l,   top.g.x, top.g.y, \
            mid.l,   mid.g.y, bot.l,   bot.g.x, bot.g.y);                \
        upd(hist, tid, hot0, hot255, mid.g.y, top.g.x, top.g.y, top.g.z, \
            mid.g.x, mid.g.z, bot.g.x, bot.g.y, bot.g.z);                \
        upd(hist, tid, hot0, hot255, mid.g.z, top.g.y, top.g.z, top.g.w, \
            mid.g.y, mid.g.w, bot.g.y, bot.g.z, bot.g.w);                \
        upd(hist, tid, hot0, hot255, mid.g.w, top.g.z, top.g.w, top.r,   \
            mid.g.z, mid.r,   bot.g.z, bot.g.w, bot.r);                  \
    } while (0)

extern "C" __global__ void __launch_bounds__(THREADS, 7)
lbp_main(const float* __restrict__ img, float* __restrict__ out) {
    extern __shared__ unsigned char hist[];   // 32 KB: hist[code*128 + byte]
    __shared__ float sh[THREADS];
    __shared__ int s_last;
    const int tid = threadIdx.x;
    const int lane = tid & 31;

    uint4* h4 = (uint4*)hist;
#pragma unroll
    for (int i = 0; i < 16; i++)
        h4[tid + i * THREADS] = make_uint4(0u, 0u, 0u, 0u);
    __syncthreads();

    // ---- one statically assigned row-segment per warp ----
    const int w = blockIdx.x * 4 + (tid >> 5);    // 0..4143
    int col, nseg, s;
    if (w < COLS_33 * 33) { col = w / 33; nseg = 33; s = w - col * 33; }
    else { int w2 = w - COLS_33 * 33; col = COLS_33 + w2 / 32; nseg = 32;
           s = w2 - (col - COLS_33) * 32; }
    const int ra = (s * IMG_H) / nseg;            // first center row
    const int rb = ((s + 1) * IMG_H) / nseg;      // one past last center row
    const int c0 = (col & 7) << 7;                // strip column base
    const float* chan = img + (size_t)(col >> 3) * 3 * HW;

    // warp-constant halo predicate + pointers (row ra-1)
    const bool ph = ((lane == 0) & (c0 > 0)) | ((lane == 31) & (c0 + 128 < IMG_W));
    const int hc = (lane == 0) ? (c0 - 1) : (c0 + 128);
    const float4* p = (const float4*)(chan + c0) + (long)(ra - 1) * W4 + lane;
    const float* qh = chan + (long)(ra - 1) * IMG_W + hc;

    unsigned hot0 = 0u, hot255 = 0u;

    // ---- prologue: prime window + 2-deep raw prefetch (guarded rows) ----
    Raw A = load_guard(p, qh, ph, ra - 1, rb); p += W4; qh += IMG_W;
    Raw B = load_guard(p, qh, ph, ra,     rb); p += W4; qh += IMG_W;
    Row top = conv(A, lane);
    A = load_guard(p, qh, ph, ra + 1, rb); p += W4; qh += IMG_W;
    Row mid = conv(B, lane);
    B = load_guard(p, qh, ph, ra + 2, rb); p += W4; qh += IMG_W;
    Row bot = conv(A, lane);
    A = load_guard(p, qh, ph, ra + 3, rb); p += W4; qh += IMG_W;
    // invariant at loop top (center r): B = raw(r+2), A = raw(r+3),
    // p/qh point at row r+4.

    int r = ra;
    const int rmain = rb - 4;     // rows r+4 <= rb-1 are unconditionally valid
#pragma unroll 6
    for (; r < rmain; r++) {
        DO4UPDS();
        Row nx = conv(B, lane);
        B = A;
        A = load_fast(p, qh, ph); p += W4; qh += IMG_W;
        top = mid; mid = bot; bot = nx;
    }
    for (; r < rb; r++) {         // last 4 centers: guarded loads
        DO4UPDS();
        Row nx = conv(B, lane);
        B = A;
        A = load_guard(p, qh, ph, r + 4, rb); p += W4; qh += IMG_W;
        top = mid; mid = bot; bot = nx;
    }

    // hot-code register counters: warp reduce, one atomic per warp
    unsigned t0 = __reduce_add_sync(0xffffffffu, hot0);
    unsigned t255 = __reduce_add_sync(0xffffffffu, hot255);
    if (lane == 0) {
        atomicAdd(&g_count[0], t0);
        atomicAdd(&g_count[255], t255);
    }
    __syncthreads();

    // Block reduction: thread tid sums code blocks tid and tid+128
    // (32 words each, rotated start -> conflict-free). XOR swizzle is a
    // per-code bijection of the 128 bytes, so block sums are unchanged.
    const unsigned int* h32 = (const unsigned int*)hist;
    unsigned sum0 = 0, sum1 = 0;
#pragma unroll 8
    for (int j = 0; j < 32; j++) {
        int k = (tid + j) & 31;
        sum0 = __dp4a(h32[(tid << 5) + k], 0x01010101u, sum0);
        sum1 = __dp4a(h32[((tid + 128) << 5) + k], 0x01010101u, sum1);
    }
    atomicAdd(&g_count[tid], sum0);
    atomicAdd(&g_count[tid + 128], sum1);

    // ---- last-block finalize (fused standardization) ----
    __threadfence();
    if (tid == 0) {
        unsigned d = atomicAdd(&g_done, 1u);
        s_last = (d == BLOCKS - 1);
    }
    __syncthreads();
    if (!s_last) return;

    // read-and-zero counters so every graph replay starts clean
    float h0 = (float)atomicExch(&g_count[tid], 0u);
    float h1 = (float)atomicExch(&g_count[tid + 128], 0u);

    sh[tid] = h0 + h1;
    __syncthreads();
    for (int s2 = 64; s2 > 0; s2 >>= 1) {
        if (tid < s2) sh[tid] += sh[tid + s2];
        __syncthreads();
    }
    const float mean = sh[0] * (1.0f / 256.0f);
    __syncthreads();

    const float d0 = h0 - mean, d1 = h1 - mean;
    sh[tid] = d0 * d0 + d1 * d1;
    __syncthreads();
    for (int s2 = 64; s2 > 0; s2 >>= 1) {
        if (tid < s2) sh[tid] += sh[tid + s2];
        __syncthreads();
    }
    const float stdv = sqrtf(sh[0] * (1.0f / 255.0f));   // ddof = 1
    out[tid] = d0 / stdv;
    out[tid + 128] = d1 / stdv;

    if (tid == 0) g_done = 0u;   // reset for next graph replay
}

extern "C" void kernel_launch(void* const* d_in, const int* in_sizes, int n_in,
                              void* d_out, int out_size) {
    (void)in_sizes; (void)n_in; (void)out_size;
    const float* img = (const float*)d_in[0];
    float* out = (float*)d_out;

    cudaFuncSetAttribute(lbp_main, cudaFuncAttributeMaxDynamicSharedMemorySize,
                         HIST_BYTES);
    lbp_main<<<BLOCKS, THREADS, HIST_BYTES>>>(img, out);
}

// round 16
// speedup vs baseline: 1.2075x; 1.2075x over previous
#include <cuda_runtime.h>

// ---------------------------------------------------------------------------
// LBP histogram kernel, GB300 sm_103a — round 15
// img: [16,3,1024,1024] fp32 -> out: [1,256] fp32 standardized histogram
// R12 proven shape (256 thr x 444 blocks x 64 KB hist, one segment per warp,
// one full wave at 3 blocks/SM) + hot-code (0/255) register counters.
// prmt+dp4a code builder, XOR-swizzled per-thread byte histograms, fused
// finalize.
// ---------------------------------------------------------------------------

#define IMG_H 1024
#define IMG_W 1024
#define HW (IMG_H * IMG_W)
#define W4 (IMG_W >> 2)

#define THREADS 256
#define BLOCKS 444                  // 148 SMs * 3 blocks = one full wave
// 128 (image,strip) columns; 96 cols -> 28 row-segments, 32 cols -> 27:
// 96*28 + 32*27 = 3552 segments == total warps. One segment per warp.
#define COLS_28 96

__device__ unsigned int g_count[256];
__device__ unsigned int g_done;

struct Row { float4 g; float l, r; };
struct Raw { float4 r, g, b; float hr, hg, hb; };

__device__ __forceinline__ float gray1(float r, float g, float b) {
    return fmaf(0.114f, b, fmaf(0.587f, g, 0.299f * r));
}

// PTX prmt.b32 default mode: selector nibble 0x8|i replicates the sign (msb)
// of source byte i across the destination byte (PTX ISA guaranteed).
template <unsigned SEL>
__device__ __forceinline__ unsigned prmt(unsigned a, unsigned b) {
    unsigned d;
    asm("prmt.b32 %0, %1, %2, %3;" : "=r"(d) : "r"(a), "r"(b), "n"(SEL));
    return d;
}

// Steady-state row load: unconditional bulk, predicated halo (warp-constant).
__device__ __forceinline__ Raw load_fast(const float4* __restrict__ p,
                                         const float* __restrict__ qh,
                                         bool ph) {
    Raw o;
    o.r = p[0];
    o.g = p[HW >> 2];
    o.b = p[HW >> 1];
    o.hr = o.hg = o.hb = 0.f;
    if (ph) { o.hr = qh[0]; o.hg = qh[HW]; o.hb = qh[2 * HW]; }
    return o;
}

// Edge row load: zero-fills out-of-range / out-of-segment rows.
__device__ __forceinline__ Raw load_guard(const float4* __restrict__ p,
                                          const float* __restrict__ qh,
                                          bool ph, int x, int rb) {
    Raw o;
    o.r = o.g = o.b = make_float4(0.f, 0.f, 0.f, 0.f);
    o.hr = o.hg = o.hb = 0.f;
    if ((unsigned)x < (unsigned)IMG_H && x <= rb) {
        o.r = p[0];
        o.g = p[HW >> 2];
        o.b = p[HW >> 1];
        if (ph) { o.hr = qh[0]; o.hg = qh[HW]; o.hb = qh[2 * HW]; }
    }
    return o;
}

// Convert a raw row (loaded ~2 iterations ago) to gray + neighbor shuffles.
__device__ __forceinline__ Row conv(const Raw& a, int lane) {
    Row o;
    o.g.x = gray1(a.r.x, a.g.x, a.b.x);
    o.g.y = gray1(a.r.y, a.g.y, a.b.y);
    o.g.z = gray1(a.r.z, a.g.z, a.b.z);
    o.g.w = gray1(a.r.w, a.g.w, a.b.w);
    float h = gray1(a.hr, a.hg, a.hb);      // 0 when no halo
    float sl = __shfl_up_sync(0xffffffffu, o.g.w, 1);
    float sr = __shfl_down_sync(0xffffffffu, o.g.x, 1);
    o.l = (lane == 0) ? h : sl;
    o.r = (lane == 31) ? h : sr;
    return o;
}

// LBP code via prmt sign-replication + DP4A byte-sum.
// bit_i = (n_i >= c) = NOT sign(n_i - c); grays >= 0, x-x = +0, so exact.
// Codes 0 and 255 (~11% each on this input) are counted in registers; only
// the remaining ~78% touch the smem histogram RMW chain.
__device__ __forceinline__ void upd(unsigned char* __restrict__ hist, int tid,
                                    unsigned& hot0, unsigned& hot255,
                                    float c, float tl, float t, float tr,
                                    float l, float rr, float bl, float b,
                                    float br) {
    unsigned d0 = __float_as_uint(tr - c);   // bit 0
    unsigned d1 = __float_as_uint(rr - c);   // bit 1
    unsigned d2 = __float_as_uint(br - c);   // bit 2
    unsigned d3 = __float_as_uint(b  - c);   // bit 3
    unsigned d4 = __float_as_uint(bl - c);   // bit 4
    unsigned d5 = __float_as_uint(l  - c);   // bit 5
    unsigned d6 = __float_as_uint(tl - c);   // bit 6
    unsigned d7 = __float_as_uint(t  - c);   // bit 7
    unsigned p01 = prmt<0x00FBu>(d0, d1);
    unsigned p23 = prmt<0xFB00u>(d2, d3);
    unsigned mlo = prmt<0x7610u>(p01, p23);  // [s0,s1,s2,s3]
    unsigned p45 = prmt<0x00FBu>(d4, d5);
    unsigned p67 = prmt<0xFB00u>(d6, d7);
    unsigned mhi = prmt<0x7610u>(p45, p67);  // [s4,s5,s6,s7]
    unsigned lo = ~mlo & 0x08040201u;
    unsigned hi = ~mhi & 0x80402010u;
    unsigned code = __dp4a(lo, 0x01010101u, __dp4a(hi, 0x01010101u, 0u));
    hot0   += (code == 0u);
    hot255 += (code == 255u);
    if (code - 1u < 254u)   // predicated RMW, no branch
        hist[(code << 8) + (tid ^ ((code << 2) & 255u))]++;
}

#define DO4UPDS()                                                        \
    do {                                                                 \
        upd(hist, tid, hot0, hot255, mid.g.x, top.l,   top.g.x, top.g.y, \
            mid.l,   mid.g.y, bot.l,   bot.g.x, bot.g.y);                \
        upd(hist, tid, hot0, hot255, mid.g.y, top.g.x, top.g.y, top.g.z, \
            mid.g.x, mid.g.z, bot.g.x, bot.g.y, bot.g.z);                \
        upd(hist, tid, hot0, hot255, mid.g.z, top.g.y, top.g.z, top.g.w, \
            mid.g.y, mid.g.w, bot.g.y, bot.g.z, bot.g.w);                \
        upd(hist, tid, hot0, hot255, mid.g.w, top.g.z, top.g.w, top.r,   \
            mid.g.z, mid.r,   bot.g.z, bot.g.w, bot.r);                  \
    } while (0)

extern "C" __global__ void __launch_bounds__(THREADS, 3)
lbp_main(const float* __restrict__ img, float* __restrict__ out) {
    extern __shared__ unsigned char hist[];   // 64 KB: hist[code*256 + byte]
    __shared__ float sh[256];
    __shared__ int s_last;
    const int tid = threadIdx.x;
    const int lane = tid & 31;

    uint4* h4 = (uint4*)hist;
#pragma unroll
    for (int i = 0; i < 16; i++)
        h4[tid + i * THREADS] = make_uint4(0u, 0u, 0u, 0u);
    __syncthreads();

    // ---- one statically assigned row-segment per warp ----
    const int w = blockIdx.x * 8 + (tid >> 5);    // 0..3551
    int col, nseg, s;
    if (w < COLS_28 * 28) { col = w / 28; nseg = 28; s = w - col * 28; }
    else { int w2 = w - COLS_28 * 28; col = COLS_28 + w2 / 27; nseg = 27;
           s = w2 - (col - COLS_28) * 27; }
    const int ra = (s * IMG_H) / nseg;            // first center row
    const int rb = ((s + 1) * IMG_H) / nseg;      // one past last center row
    const int c0 = (col & 7) << 7;                // strip column base
    const float* chan = img + (size_t)(col >> 3) * 3 * HW;

    // warp-constant halo predicate + pointers (row ra-1)
    const bool ph = ((lane == 0) & (c0 > 0)) | ((lane == 31) & (c0 + 128 < IMG_W));
    const int hc = (lane == 0) ? (c0 - 1) : (c0 + 128);
    const float4* p = (const float4*)(chan + c0) + (long)(ra - 1) * W4 + lane;
    const float* qh = chan + (long)(ra - 1) * IMG_W + hc;

    unsigned hot0 = 0u, hot255 = 0u;

    // ---- prologue: prime window + 2-deep raw prefetch (guarded rows) ----
    Raw A = load_guard(p, qh, ph, ra - 1, rb); p += W4; qh += IMG_W;
    Raw B = load_guard(p, qh, ph, ra,     rb); p += W4; qh += IMG_W;
    Row top = conv(A, lane);
    A = load_guard(p, qh, ph, ra + 1, rb); p += W4; qh += IMG_W;
    Row mid = conv(B, lane);
    B = load_guard(p, qh, ph, ra + 2, rb); p += W4; qh += IMG_W;
    Row bot = conv(A, lane);
    A = load_guard(p, qh, ph, ra + 3, rb); p += W4; qh += IMG_W;
    // invariant at loop top (center r): B = raw(r+2), A = raw(r+3),
    // p/qh point at row r+4.

    int r = ra;
    const int rmain = rb - 4;     // rows r+4 <= rb-1 are unconditionally valid
#pragma unroll 6
    for (; r < rmain; r++) {
        DO4UPDS();
        Row nx = conv(B, lane);
        B = A;
        A = load_fast(p, qh, ph); p += W4; qh += IMG_W;
        top = mid; mid = bot; bot = nx;
    }
    for (; r < rb; r++) {         // last 4 centers: guarded loads
        DO4UPDS();
        Row nx = conv(B, lane);
        B = A;
        A = load_guard(p, qh, ph, r + 4, rb); p += W4; qh += IMG_W;
        top = mid; mid = bot; bot = nx;
    }

    // hot-code register counters: warp reduce, one atomic per warp
    unsigned t0 = __reduce_add_sync(0xffffffffu, hot0);
    unsigned t255 = __reduce_add_sync(0xffffffffu, hot255);
    if (lane == 0) {
        atomicAdd(&g_count[0], t0);
        atomicAdd(&g_count[255], t255);
    }
    __syncthreads();

    // Block reduction: thread tid sums code block tid (64 words, rotated
    // start -> conflict-free). XOR swizzle is a per-code bijection of the
    // 256 bytes, so block sums are unchanged.
    const unsigned int* h32 = (const unsigned int*)hist;
    unsigned int sum = 0;
    const int wbase = tid << 6;
#pragma unroll 8
    for (int j = 0; j < 64; j++) {
        unsigned int v = h32[wbase + ((tid + j) & 63)];
        sum = __dp4a(v, 0x01010101u, sum);
    }
    atomicAdd(&g_count[tid], sum);

    // ---- last-block finalize (fused standardization) ----
    __threadfence();
    if (tid == 0) {
        unsigned d = atomicAdd(&g_done, 1u);
        s_last = (d == BLOCKS - 1);
    }
    __syncthreads();
    if (!s_last) return;

    // read-and-zero counters so every graph replay starts clean
    float h = (float)atomicExch(&g_count[tid], 0u);

    sh[tid] = h;
    __syncthreads();
    for (int s2 = 128; s2 > 0; s2 >>= 1) {
        if (tid < s2) sh[tid] += sh[tid + s2];
        __syncthreads();
    }
    const float mean = sh[0] * (1.0f / 256.0f);
    __syncthreads();

    const float d = h - mean;
    sh[tid] = d * d;
    __syncthreads();
    for (int s2 = 128; s2 > 0; s2 >>= 1) {
        if (tid < s2) sh[tid] += sh[tid + s2];
        __syncthreads();
    }
    const float stdv = sqrtf(sh[0] * (1.0f / 255.0f));   // ddof = 1
    out[tid] = d / stdv;

    if (tid == 0) g_done = 0u;   // reset for next graph replay
}

extern "C" void kernel_launch(void* const* d_in, const int* in_sizes, int n_in,
                              void* d_out, int out_size) {
    (void)in_sizes; (void)n_in; (void)out_size;
    const float* img = (const float*)d_in[0];
    float* out = (float*)d_out;

    cudaFuncSetAttribute(lbp_main, cudaFuncAttributeMaxDynamicSharedMemorySize,
                         65536);
    lbp_main<<<BLOCKS, THREADS, 65536>>>(img, out);
}

// round 17
// speedup vs baseline: 1.3060x; 1.0816x over previous
#include <cuda_runtime.h>

// ---------------------------------------------------------------------------
// LBP histogram kernel, GB300 sm_103a — round 16
// img: [16,3,1024,1024] fp32 -> out: [1,256] fp32 standardized histogram
// R12 shape (256 thr x 444 blocks x 64 KB, one segment per warp, one wave)
// + batched histogram RMW: 4 pipelined LDS.U8, register collision chaining,
// 4 STS.U8 — removes the alias-serialized ld->st->ld->st chain.
// prmt+dp4a code builder, XOR-swizzled per-thread byte histograms, fused
// finalize.
// ---------------------------------------------------------------------------

#define IMG_H 1024
#define IMG_W 1024
#define HW (IMG_H * IMG_W)
#define W4 (IMG_W >> 2)

#define THREADS 256
#define BLOCKS 444                  // 148 SMs * 3 blocks = one full wave
// 128 (image,strip) columns; 96 cols -> 28 row-segments, 32 cols -> 27:
// 96*28 + 32*27 = 3552 segments == total warps. One segment per warp.
#define COLS_28 96

__device__ unsigned int g_count[256];
__device__ unsigned int g_done;

struct Row { float4 g; float l, r; };
struct Raw { float4 r, g, b; float hr, hg, hb; };

__device__ __forceinline__ float gray1(float r, float g, float b) {
    return fmaf(0.114f, b, fmaf(0.587f, g, 0.299f * r));
}

// PTX prmt.b32 default mode: selector nibble 0x8|i replicates the sign (msb)
// of source byte i across the destination byte (PTX ISA guaranteed).
template <unsigned SEL>
__device__ __forceinline__ unsigned prmt(unsigned a, unsigned b) {
    unsigned d;
    asm("prmt.b32 %0, %1, %2, %3;" : "=r"(d) : "r"(a), "r"(b), "n"(SEL));
    return d;
}

// Steady-state row load: unconditional bulk, predicated halo (warp-constant).
__device__ __forceinline__ Raw load_fast(const float4* __restrict__ p,
                                         const float* __restrict__ qh,
                                         bool ph) {
    Raw o;
    o.r = p[0];
    o.g = p[HW >> 2];
    o.b = p[HW >> 1];
    o.hr = o.hg = o.hb = 0.f;
    if (ph) { o.hr = qh[0]; o.hg = qh[HW]; o.hb = qh[2 * HW]; }
    return o;
}

// Edge row load: zero-fills out-of-range / out-of-segment rows.
__device__ __forceinline__ Raw load_guard(const float4* __restrict__ p,
                                          const float* __restrict__ qh,
                                          bool ph, int x, int rb) {
    Raw o;
    o.r = o.g = o.b = make_float4(0.f, 0.f, 0.f, 0.f);
    o.hr = o.hg = o.hb = 0.f;
    if ((unsigned)x < (unsigned)IMG_H && x <= rb) {
        o.r = p[0];
        o.g = p[HW >> 2];
        o.b = p[HW >> 1];
        if (ph) { o.hr = qh[0]; o.hg = qh[HW]; o.hb = qh[2 * HW]; }
    }
    return o;
}

// Convert a raw row (loaded ~2 iterations ago) to gray + neighbor shuffles.
__device__ __forceinline__ Row conv(const Raw& a, int lane) {
    Row o;
    o.g.x = gray1(a.r.x, a.g.x, a.b.x);
    o.g.y = gray1(a.r.y, a.g.y, a.b.y);
    o.g.z = gray1(a.r.z, a.g.z, a.b.z);
    o.g.w = gray1(a.r.w, a.g.w, a.b.w);
    float h = gray1(a.hr, a.hg, a.hb);      // 0 when no halo
    float sl = __shfl_up_sync(0xffffffffu, o.g.w, 1);
    float sr = __shfl_down_sync(0xffffffffu, o.g.x, 1);
    o.l = (lane == 0) ? h : sl;
    o.r = (lane == 31) ? h : sr;
    return o;
}

// LBP code via prmt sign-replication + DP4A byte-sum.
// bit_i = (n_i >= c) = NOT sign(n_i - c); grays >= 0, x-x = +0, so exact.
__device__ __forceinline__ unsigned lbp_code(float c, float tl, float t,
                                             float tr, float l, float rr,
                                             float bl, float b, float br) {
    unsigned d0 = __float_as_uint(tr - c);   // bit 0
    unsigned d1 = __float_as_uint(rr - c);   // bit 1
    unsigned d2 = __float_as_uint(br - c);   // bit 2
    unsigned d3 = __float_as_uint(b  - c);   // bit 3
    unsigned d4 = __float_as_uint(bl - c);   // bit 4
    unsigned d5 = __float_as_uint(l  - c);   // bit 5
    unsigned d6 = __float_as_uint(tl - c);   // bit 6
    unsigned d7 = __float_as_uint(t  - c);   // bit 7
    unsigned p01 = prmt<0x00FBu>(d0, d1);
    unsigned p23 = prmt<0xFB00u>(d2, d3);
    unsigned mlo = prmt<0x7610u>(p01, p23);  // [s0,s1,s2,s3]
    unsigned p45 = prmt<0x00FBu>(d4, d5);
    unsigned p67 = prmt<0xFB00u>(d6, d7);
    unsigned mhi = prmt<0x7610u>(p45, p67);  // [s4,s5,s6,s7]
    unsigned lo = ~mlo & 0x08040201u;
    unsigned hi = ~mhi & 0x80402010u;
    return __dp4a(lo, 0x01010101u, __dp4a(hi, 0x01010101u, 0u));
}

// XOR swizzle: per-code bijection of the 256 bytes; equal codes in a
// lane-quad share a word (distinct bytes), distinct codes spread banks.
__device__ __forceinline__ unsigned haddr(unsigned code, int tid) {
    return (code << 8) + ((unsigned)tid ^ ((code << 2) & 255u));
}

// Batched quad histogram update. All 4 LDS issue before any STS (pipelined
// latency); same-address collisions (same code in this thread's 4 pixels)
// are chained in registers, and in-order STS makes the last store carry the
// accumulated count -> exact for every collision pattern.
#define DO4UPDS()                                                          \
    do {                                                                   \
        unsigned c0 = lbp_code(mid.g.x, top.l,   top.g.x, top.g.y,         \
                               mid.l,   mid.g.y, bot.l,   bot.g.x, bot.g.y);\
        unsigned c1 = lbp_code(mid.g.y, top.g.x, top.g.y, top.g.z,         \
                               mid.g.x, mid.g.z, bot.g.x, bot.g.y, bot.g.z);\
        unsigned c2 = lbp_code(mid.g.z, top.g.y, top.g.z, top.g.w,         \
                               mid.g.y, mid.g.w, bot.g.y, bot.g.z, bot.g.w);\
        unsigned c3 = lbp_code(mid.g.w, top.g.z, top.g.w, top.r,           \
                               mid.g.z, mid.r,   bot.g.z, bot.g.w, bot.r); \
        unsigned a0 = haddr(c0, tid), a1 = haddr(c1, tid);                 \
        unsigned a2 = haddr(c2, tid), a3 = haddr(c3, tid);                 \
        unsigned v0 = hist[a0], v1 = hist[a1];                             \
        unsigned v2 = hist[a2], v3 = hist[a3];                             \
        unsigned n0 = v0 + 1u;                                             \
        unsigned n1 = ((a1 == a0) ? n0 : v1) + 1u;                         \
        unsigned n2 = ((a2 == a1) ? n1 : (a2 == a0) ? n0 : v2) + 1u;       \
        unsigned n3 = ((a3 == a2) ? n2 : (a3 == a1) ? n1 :                 \
                       (a3 == a0) ? n0 : v3) + 1u;                         \
        hist[a0] = (unsigned char)n0;                                      \
        hist[a1] = (unsigned char)n1;                                      \
        hist[a2] = (unsigned char)n2;                                      \
        hist[a3] = (unsigned char)n3;                                      \
    } while (0)

extern "C" __global__ void __launch_bounds__(THREADS, 3)
lbp_main(const float* __restrict__ img, float* __restrict__ out) {
    extern __shared__ unsigned char hist[];   // 64 KB: hist[code*256 + byte]
    __shared__ float sh[256];
    __shared__ int s_last;
    const int tid = threadIdx.x;
    const int lane = tid & 31;

    uint4* h4 = (uint4*)hist;
#pragma unroll
    for (int i = 0; i < 16; i++)
        h4[tid + i * THREADS] = make_uint4(0u, 0u, 0u, 0u);
    __syncthreads();

    // ---- one statically assigned row-segment per warp ----
    const int w = blockIdx.x * 8 + (tid >> 5);    // 0..3551
    int col, nseg, s;
    if (w < COLS_28 * 28) { col = w / 28; nseg = 28; s = w - col * 28; }
    else { int w2 = w - COLS_28 * 28; col = COLS_28 + w2 / 27; nseg = 27;
           s = w2 - (col - COLS_28) * 27; }
    const int ra = (s * IMG_H) / nseg;            // first center row
    const int rb = ((s + 1) * IMG_H) / nseg;      // one past last center row
    const int c0s = (col & 7) << 7;               // strip column base
    const float* chan = img + (size_t)(col >> 3) * 3 * HW;

    // warp-constant halo predicate + pointers (row ra-1)
    const bool ph = ((lane == 0) & (c0s > 0)) |
                    ((lane == 31) & (c0s + 128 < IMG_W));
    const int hc = (lane == 0) ? (c0s - 1) : (c0s + 128);
    const float4* p = (const float4*)(chan + c0s) + (long)(ra - 1) * W4 + lane;
    const float* qh = chan + (long)(ra - 1) * IMG_W + hc;

    // ---- prologue: prime window + 2-deep raw prefetch (guarded rows) ----
    Raw A = load_guard(p, qh, ph, ra - 1, rb); p += W4; qh += IMG_W;
    Raw B = load_guard(p, qh, ph, ra,     rb); p += W4; qh += IMG_W;
    Row top = conv(A, lane);
    A = load_guard(p, qh, ph, ra + 1, rb); p += W4; qh += IMG_W;
    Row mid = conv(B, lane);
    B = load_guard(p, qh, ph, ra + 2, rb); p += W4; qh += IMG_W;
    Row bot = conv(A, lane);
    A = load_guard(p, qh, ph, ra + 3, rb); p += W4; qh += IMG_W;
    // invariant at loop top (center r): B = raw(r+2), A = raw(r+3),
    // p/qh point at row r+4.

    int r = ra;
    const int rmain = rb - 4;     // rows r+4 <= rb-1 are unconditionally valid
#pragma unroll 6
    for (; r < rmain; r++) {
        DO4UPDS();
        Row nx = conv(B, lane);
        B = A;
        A = load_fast(p, qh, ph); p += W4; qh += IMG_W;
        top = mid; mid = bot; bot = nx;
    }
    for (; r < rb; r++) {         // last 4 centers: guarded loads
        DO4UPDS();
        Row nx = conv(B, lane);
        B = A;
        A = load_guard(p, qh, ph, r + 4, rb); p += W4; qh += IMG_W;
        top = mid; mid = bot; bot = nx;
    }
    __syncthreads();

    // Block reduction: thread tid sums code block tid (64 words, rotated
    // start -> conflict-free). XOR swizzle is a per-code bijection of the
    // 256 bytes, so block sums are unchanged.
    const unsigned int* h32 = (const unsigned int*)hist;
    unsigned int sum = 0;
    const int wbase = tid << 6;
#pragma unroll 8
    for (int j = 0; j < 64; j++) {
        unsigned int v = h32[wbase + ((tid + j) & 63)];
        sum = __dp4a(v, 0x01010101u, sum);
    }
    atomicAdd(&g_count[tid], sum);

    // ---- last-block finalize (fused standardization) ----
    __threadfence();
    if (tid == 0) {
        unsigned d = atomicAdd(&g_done, 1u);
        s_last = (d == BLOCKS - 1);
    }
    __syncthreads();
    if (!s_last) return;

    // read-and-zero counters so every graph replay starts clean
    float h = (float)atomicExch(&g_count[tid], 0u);

    sh[tid] = h;
    __syncthreads();
    for (int s2 = 128; s2 > 0; s2 >>= 1) {
        if (tid < s2) sh[tid] += sh[tid + s2];
        __syncthreads();
    }
    const float mean = sh[0] * (1.0f / 256.0f);
    __syncthreads();

    const float d = h - mean;
    sh[tid] = d * d;
    __syncthreads();
    for (int s2 = 128; s2 > 0; s2 >>= 1) {
        if (tid < s2) sh[tid] += sh[tid + s2];
        __syncthreads();
    }
    const float stdv = sqrtf(sh[0] * (1.0f / 255.0f));   // ddof = 1
    out[tid] = d / stdv;

    if (tid == 0) g_done = 0u;   // reset for next graph replay
}

extern "C" void kernel_launch(void* const* d_in, const int* in_sizes, int n_in,
                              void* d_out, int out_size) {
    (void)in_sizes; (void)n_in; (void)out_size;
    const float* img = (const float*)d_in[0];
    float* out = (float*)d_out;

    cudaFuncSetAttribute(lbp_main, cudaFuncAttributeMaxDynamicSharedMemorySize,
                         65536);
    lbp_main<<<BLOCKS, THREADS, 65536>>>(img, out);
}